// round 6
// baseline (speedup 1.0000x reference)
#include <cuda_runtime.h>
#include <cuda_bf16.h>
#include <math.h>
#include <stdint.h>

#define NROWS 8192
#define FIN   128
#define FOUT  64
#define BI    64
#define BJ    128
#define TILES 64
#define L2E 1.4426950408889634f
#define PB  272                  // smem row pitch in bytes (136 bf16)

// attn smem map (bytes)
#define SM_P   0                 // 2 bufs x (2 planes x 17408) = 69632
#define SM_WH  69632             // 3 bufs x 34816 = 104448
#define SM_LR  174080            // 512 floats
#define SM_TOTB 176128

typedef unsigned long long ull;

__device__ float g_Wh1[NROWS];
__device__ float g_Wh2[NROWS];
__device__ __nv_bfloat16 g_WhT_hi[FOUT * NROWS];
__device__ __nv_bfloat16 g_WhT_lo[FOUT * NROWS];

// ---- helpers ----------------------------------------------------------------
__device__ __forceinline__ uint32_t s2u(const void* p) {
    uint32_t a;
    asm("{.reg .u64 t; cvta.to.shared.u64 t,%1; cvt.u32.u64 %0,t;}" : "=r"(a) : "l"(p));
    return a;
}
__device__ __forceinline__ float ex2f(float x) {
    float y; asm("ex2.approx.ftz.f32 %0,%1;" : "=f"(y) : "f"(x)); return y;
}
__device__ __forceinline__ uint32_t bf2(float a, float b) {   // lo=a, hi=b
    uint32_t r; asm("cvt.rn.bf16x2.f32 %0,%2,%1;" : "=r"(r) : "f"(a), "f"(b)); return r;
}
__device__ __forceinline__ void cpasync16(uint32_t d, const void* s) {
    asm volatile("cp.async.cg.shared.global [%0],[%1],16;" :: "r"(d), "l"(s));
}
__device__ __forceinline__ void ldsm4(uint32_t* r, uint32_t a) {
    asm volatile("ldmatrix.sync.aligned.m8n8.x4.shared.b16 {%0,%1,%2,%3},[%4];"
                 : "=r"(r[0]), "=r"(r[1]), "=r"(r[2]), "=r"(r[3]) : "r"(a));
}
__device__ __forceinline__ void mmabf(float* d, const uint32_t* a, const uint32_t* b) {
    asm volatile("mma.sync.aligned.m16n8k16.row.col.f32.bf16.bf16.f32 "
                 "{%0,%1,%2,%3},{%4,%5,%6,%7},{%8,%9},{%0,%1,%2,%3};"
                 : "+f"(d[0]), "+f"(d[1]), "+f"(d[2]), "+f"(d[3])
                 : "r"(a[0]), "r"(a[1]), "r"(a[2]), "r"(a[3]), "r"(b[0]), "r"(b[1]));
}
__device__ __forceinline__ ull packf2(float a, float b) {
    ull r;
    asm("mov.b64 %0,{%1,%2};" : "=l"(r) : "r"(__float_as_uint(a)), "r"(__float_as_uint(b)));
    return r;
}
__device__ __forceinline__ void fmaf2(ull& acc, ull a, ull b) {
    asm("fma.rn.f32x2 %0,%1,%2,%0;" : "+l"(acc) : "l"(a), "l"(b));
}
__device__ __forceinline__ void unpackf2(ull v, float& lo, float& hi) {
    uint32_t l, h;
    asm("mov.b64 {%0,%1},%2;" : "=r"(l), "=r"(h) : "l"(v));
    lo = __uint_as_float(l); hi = __uint_as_float(h);
}

// phase-1: 16 cols for one row -> P hi/lo planes, accumulate lsum
__device__ __forceinline__ void phase1_store(char* ph, const int4* cur,
                                             const float4* w2, float wh1r,
                                             float& lsum) {
    const float NEGI = __int_as_float(0xff800000);
    uint32_t hi[8], lo[8];
#pragma unroll
    for (int k = 0; k < 4; k++) {
        int4 a4 = cur[k]; float4 wv = w2[k];
        float z, u, tt, p0, p1, p2, p3;
        z = wh1r + wv.x; u = z * L2E; tt = fmaxf(u, 0.2f * u);
        if (a4.x == 0) tt = NEGI; p0 = ex2f(tt);
        z = wh1r + wv.y; u = z * L2E; tt = fmaxf(u, 0.2f * u);
        if (a4.y == 0) tt = NEGI; p1 = ex2f(tt);
        z = wh1r + wv.z; u = z * L2E; tt = fmaxf(u, 0.2f * u);
        if (a4.z == 0) tt = NEGI; p2 = ex2f(tt);
        z = wh1r + wv.w; u = z * L2E; tt = fmaxf(u, 0.2f * u);
        if (a4.w == 0) tt = NEGI; p3 = ex2f(tt);
        lsum += (p0 + p1) + (p2 + p3);
        uint32_t h0 = bf2(p0, p1), h1 = bf2(p2, p3);
        float r0 = p0 - __uint_as_float(h0 << 16);
        float r1 = p1 - __uint_as_float(h0 & 0xffff0000u);
        float r2 = p2 - __uint_as_float(h1 << 16);
        float r3 = p3 - __uint_as_float(h1 & 0xffff0000u);
        hi[2 * k] = h0; hi[2 * k + 1] = h1;
        lo[2 * k] = bf2(r0, r1); lo[2 * k + 1] = bf2(r2, r3);
    }
    *(uint4*)ph = make_uint4(hi[0], hi[1], hi[2], hi[3]);
    *(uint4*)(ph + 16) = make_uint4(hi[4], hi[5], hi[6], hi[7]);
    *(uint4*)(ph + 17408) = make_uint4(lo[0], lo[1], lo[2], lo[3]);
    *(uint4*)(ph + 17408 + 16) = make_uint4(lo[4], lo[5], lo[6], lo[7]);
}

// ---------------------------------------------------------------------------
// Fused prep: Wh = x@W -> WhT hi/lo planes, Wh1, Wh2. 64 rows/block, grid 128.
// ---------------------------------------------------------------------------
__global__ __launch_bounds__(256) void wh_fused(const float* __restrict__ x,
                                                const float* __restrict__ W,
                                                const float* __restrict__ a) {
    extern __shared__ float shm[];
    float* xs = shm;                  // 64 x 132
    float* Ws = shm + 8448;           // 128 x 64
    float* av = shm + 8448 + 8192;    // 128
    int tid = threadIdx.x;
    int row0 = blockIdx.x * 64;

    for (int u = tid; u < 2048; u += 256) {
        int rr = u >> 5, cc = u & 31;
        float4 v = ((const float4*)(x + (size_t)(row0 + rr) * FIN))[cc];
        *(float4*)(xs + rr * 132 + cc * 4) = v;
    }
    for (int u = tid; u < 2048; u += 256)
        ((float4*)Ws)[u] = ((const float4*)W)[u];
    if (tid < 128) av[tid] = a[tid];
    __syncthreads();

    int tr = tid >> 4, tc = tid & 15;
    ull acc[4][2] = {{0ull, 0ull}, {0ull, 0ull}, {0ull, 0ull}, {0ull, 0ull}};
    const ulonglong2* W2 = (const ulonglong2*)Ws;
#pragma unroll 4
    for (int k = 0; k < FIN; k++) {
        ulonglong2 wv = W2[k * 16 + tc];
#pragma unroll
        for (int i = 0; i < 4; i++) {
            float xv = xs[(tr * 4 + i) * 132 + k];
            ull xp = packf2(xv, xv);
            fmaf2(acc[i][0], xp, wv.x);
            fmaf2(acc[i][1], xp, wv.y);
        }
    }
    float o[4][4];
#pragma unroll
    for (int i = 0; i < 4; i++) {
        unpackf2(acc[i][0], o[i][0], o[i][1]);
        unpackf2(acc[i][1], o[i][2], o[i][3]);
    }
    __syncthreads();                 // xs reads done everywhere
    float* s2 = xs;                  // reuse: [64 f][pitch 65] transposed
#pragma unroll
    for (int i = 0; i < 4; i++)
#pragma unroll
        for (int j = 0; j < 4; j++)
            s2[(tc * 4 + j) * 65 + tr * 4 + i] = o[i][j];
    __syncthreads();

    // WhT hi/lo out (coalesced along rows)
    {
        int f = tid >> 2, seg = tid & 3;
        const float* src = s2 + f * 65 + seg * 16;
        uint32_t hi[8], lo[8];
#pragma unroll
        for (int j = 0; j < 8; j++) {
            float v0 = src[2 * j], v1 = src[2 * j + 1];
            uint32_t hh = bf2(v0, v1);
            float r0 = v0 - __uint_as_float(hh << 16);
            float r1 = v1 - __uint_as_float(hh & 0xffff0000u);
            hi[j] = hh; lo[j] = bf2(r0, r1);
        }
        size_t o0 = ((size_t)f * NROWS + row0 + seg * 16) * 2;
        *(uint4*)((char*)g_WhT_hi + o0) = make_uint4(hi[0], hi[1], hi[2], hi[3]);
        *(uint4*)((char*)g_WhT_hi + o0 + 16) = make_uint4(hi[4], hi[5], hi[6], hi[7]);
        *(uint4*)((char*)g_WhT_lo + o0) = make_uint4(lo[0], lo[1], lo[2], lo[3]);
        *(uint4*)((char*)g_WhT_lo + o0 + 16) = make_uint4(lo[4], lo[5], lo[6], lo[7]);
    }
    // Wh1 / Wh2
    {
        int row = tid >> 2, sub = tid & 3;
        float s1 = 0.f, sB = 0.f;
#pragma unroll
        for (int k = 0; k < 16; k++) {
            int f = sub * 16 + k;
            float v = s2[f * 65 + row];
            s1 += v * av[f];
            sB += v * av[64 + f];
        }
        s1 += __shfl_xor_sync(0xffffffffu, s1, 1);
        s1 += __shfl_xor_sync(0xffffffffu, s1, 2);
        sB += __shfl_xor_sync(0xffffffffu, sB, 1);
        sB += __shfl_xor_sync(0xffffffffu, sB, 2);
        if (sub == 0) { g_Wh1[row0 + row] = s1; g_Wh2[row0 + row] = sB; }
    }
}

// ---------------------------------------------------------------------------
// attn: pipelined — region t does MMA(t) overlapped with phase-1(t+1).
// 512 threads; MMA: 16 warps = 4 m16-strips x 4 n16-slices.
// ---------------------------------------------------------------------------
__global__ __launch_bounds__(512, 1) void attn_kernel(const int* __restrict__ adj,
                                                      float* __restrict__ out) {
    extern __shared__ char smc[];
    uint32_t smb = s2u(smc);
    float* lred = (float*)(smc + SM_LR);

    int tid = threadIdx.x;
    int i0 = blockIdx.x * BI;

    // phase-1 mapping: 8 threads per row, 16 cols each
    int r = tid >> 3, q = tid & 7;
    const int4* arow = (const int4*)adj + (size_t)(i0 + r) * (NROWS / 4);
    float wh1r = g_Wh1[i0 + r];
    float lsum = 0.f;

    // mma mapping
    int warp = tid >> 5, lane = tid & 31;
    int s = warp >> 2, h = warp & 3;
    uint32_t aoff = (uint32_t)((((lane & 7) + 8 * ((lane >> 3) & 1)) * PB) + (lane >> 4) * 16);
    uint32_t aBase0 = smb + SM_P + s * 16 * PB + aoff;
    uint32_t boff = (uint32_t)(((lane & 7) + 8 * (lane >> 4)) * PB + ((lane >> 3) & 1) * 16);
    uint32_t bBase0 = smb + SM_WH + h * 16 * PB + boff;
    float acc[2][4] = {{0.f, 0.f, 0.f, 0.f}, {0.f, 0.f, 0.f, 0.f}};

    // cp.async geometry (tile-invariant): 2 chunks/thread/plane
    uint32_t dsto[2], srco[2];
#pragma unroll
    for (int u = 0; u < 2; u++) {
        int idx = u * 512 + tid;
        int row = idx >> 4, ch = idx & 15;
        dsto[u] = (uint32_t)(row * PB + ch * 16);
        srco[u] = (uint32_t)((row * NROWS + ch * 8) * 2);
    }

    // ---- prologue ----
    int4 cur[4];
    float4 w2v[4];
#pragma unroll
    for (int k = 0; k < 4; k++) cur[k] = arow[q * 4 + k];
#pragma unroll
    for (int k = 0; k < 4; k++) w2v[k] = ((const float4*)g_Wh2)[q * 4 + k];
#pragma unroll
    for (int b = 0; b < 2; b++) {
        uint32_t d0 = smb + SM_WH + b * 34816;
        const char* ph = (const char*)g_WhT_hi;
        const char* pl = (const char*)g_WhT_lo;
#pragma unroll
        for (int u = 0; u < 2; u++) cpasync16(d0 + dsto[u], ph + srco[u] + b * 256);
#pragma unroll
        for (int u = 0; u < 2; u++) cpasync16(d0 + 17408 + dsto[u], pl + srco[u] + b * 256);
        asm volatile("cp.async.commit_group;" ::: "memory");
    }
    phase1_store(smc + SM_P + r * PB + q * 32, cur, w2v, wh1r, lsum);
    asm volatile("cp.async.wait_group 1;" ::: "memory");
    __syncthreads();

    for (int t = 0; t < TILES; ++t) {
        if (t < 63) {
            int jn = (t + 1) << 7;
#pragma unroll
            for (int k = 0; k < 4; k++) cur[k] = arow[(jn >> 2) + q * 4 + k];
#pragma unroll
            for (int k = 0; k < 4; k++) w2v[k] = ((const float4*)g_Wh2)[(jn >> 2) + q * 4 + k];
        }
        // ---- MMA(t): P[t&1] x Wh[t%3] ----
        {
            uint32_t aB = aBase0 + (uint32_t)(t & 1) * 34816, aL = aB + 17408;
            uint32_t wB = bBase0 + (uint32_t)(t % 3) * 34816, wL = wB + 17408;
            uint32_t ah[4], al[4], bh[4], bl[4];
#pragma unroll
            for (int k = 0; k < 8; k++) {
                uint32_t ko = (uint32_t)k * 32;
                ldsm4(ah, aB + ko); ldsm4(al, aL + ko);
                ldsm4(bh, wB + ko); ldsm4(bl, wL + ko);
                mmabf(acc[0], ah, bh + 0); mmabf(acc[1], ah, bh + 2);
                mmabf(acc[0], ah, bl + 0); mmabf(acc[1], ah, bl + 2);
                mmabf(acc[0], al, bh + 0); mmabf(acc[1], al, bh + 2);
            }
        }
        // ---- phase-1(t+1) into P[(t+1)&1] ----
        if (t < 63)
            phase1_store(smc + SM_P + ((t + 1) & 1) * 34816 + r * PB + q * 32,
                         cur, w2v, wh1r, lsum);
        // ---- cp.async Wh(t+2) into buf (t+2)%3 ----
        if (t < 62) {
            int jq = t + 2;
            uint32_t d0 = smb + SM_WH + (uint32_t)(jq % 3) * 34816;
            const char* ph = (const char*)g_WhT_hi;
            const char* pl = (const char*)g_WhT_lo;
            uint32_t j2 = (uint32_t)jq * 256;
#pragma unroll
            for (int u = 0; u < 2; u++) cpasync16(d0 + dsto[u], ph + srco[u] + j2);
#pragma unroll
            for (int u = 0; u < 2; u++) cpasync16(d0 + 17408 + dsto[u], pl + srco[u] + j2);
            asm volatile("cp.async.commit_group;" ::: "memory");
            asm volatile("cp.async.wait_group 1;" ::: "memory");
        } else {
            asm volatile("cp.async.wait_group 0;" ::: "memory");
        }
        __syncthreads();
    }

    // ---- epilogue ----
    lred[tid] = lsum;
    __syncthreads();
    int r0o = s * 16 + (lane >> 2);
    float4 A = *(float4*)&lred[r0o * 8];
    float4 B = *(float4*)&lred[r0o * 8 + 4];
    float l0 = ((A.x + A.y) + (A.z + A.w)) + ((B.x + B.y) + (B.z + B.w));
    float4 C = *(float4*)&lred[(r0o + 8) * 8];
    float4 D = *(float4*)&lred[(r0o + 8) * 8 + 4];
    float l1 = ((C.x + C.y) + (C.z + C.w)) + ((D.x + D.y) + (D.z + D.w));
    float inv0 = 1.0f / l0, inv1 = 1.0f / l1;
#pragma unroll
    for (int nb = 0; nb < 2; nb++) {
        int col = h * 16 + nb * 8 + (lane & 3) * 2;
        float v0 = acc[nb][0] * inv0, v1 = acc[nb][1] * inv0;
        float v2 = acc[nb][2] * inv1, v3 = acc[nb][3] * inv1;
        v0 = v0 > 0.f ? v0 : (__expf(v0) - 1.f);
        v1 = v1 > 0.f ? v1 : (__expf(v1) - 1.f);
        v2 = v2 > 0.f ? v2 : (__expf(v2) - 1.f);
        v3 = v3 > 0.f ? v3 : (__expf(v3) - 1.f);
        *(float2*)(out + (size_t)(i0 + r0o) * FOUT + col) = make_float2(v0, v1);
        *(float2*)(out + (size_t)(i0 + r0o + 8) * FOUT + col) = make_float2(v2, v3);
    }
}

// ---------------------------------------------------------------------------
extern "C" void kernel_launch(void* const* d_in, const int* in_sizes, int n_in,
                              void* d_out, int out_size) {
    const float* x   = (const float*)d_in[0];
    const int*   adj = (const int*)d_in[1];
    const float* W   = (const float*)d_in[2];
    const float* a   = (const float*)d_in[3];
    float* out = (float*)d_out;

    size_t smem_wh = (size_t)(8448 + 8192 + 128) * sizeof(float);
    static int attr_set = 0;
    if (!attr_set) {
        cudaFuncSetAttribute(wh_fused, cudaFuncAttributeMaxDynamicSharedMemorySize,
                             (int)smem_wh);
        cudaFuncSetAttribute(attn_kernel, cudaFuncAttributeMaxDynamicSharedMemorySize,
                             SM_TOTB);
        attr_set = 1;
    }

    wh_fused<<<NROWS / 64, 256, smem_wh>>>(x, W, a);
    attn_kernel<<<NROWS / BI, 512, SM_TOTB>>>(adj, out);
}